// round 15
// baseline (speedup 1.0000x reference)
#include <cuda_runtime.h>
#include <cuda_bf16.h>
#include <cstdint>
#include <math.h>

#define N_PTS    65536
#define DIM      128
#define KCODES   1024
#define NTILES   16
#define KC       64
#define MARGIN   1e-4f
#define XS       392        // extended-K row stride (384 + 8 pad), bf16 elems
#define KEXT     384

// ============================================================
// device scratch
// ============================================================
__device__ __nv_bfloat16 g_c0[KCODES * DIM];
__device__ __nv_bfloat16 g_c1[KCODES * DIM];
__device__ float g_A[N_PTS];        // Kahan fp32 ||x||^2 (R11-proven sequence)
__device__ float g_bsq[KCODES];     // double-exact ||c||^2
__device__ int   g_counts[KCODES];
__device__ int   g_idx[N_PTS];
__device__ int   g_res[N_PTS];
__device__ int   g_nres;
__device__ float g_bloss[512];

__device__ __forceinline__ uint32_t smem_u32(const void* p) {
    uint32_t a;
    asm("{ .reg .u64 t; cvta.to.shared.u64 t, %1; cvt.u32.u64 %0, t; }" : "=r"(a) : "l"(p));
    return a;
}
__device__ __forceinline__ uint32_t pkbf(__nv_bfloat16 a, __nv_bfloat16 b) {
    return (uint32_t)__bfloat16_as_ushort(a) | ((uint32_t)__bfloat16_as_ushort(b) << 16);
}
__device__ __forceinline__ void split2(float v, __nv_bfloat16& h0, __nv_bfloat16& h1) {
    h0 = __float2bfloat16_rn(v);
    h1 = __float2bfloat16_rn(__fsub_rn(v, __bfloat162float(h0)));
}

// ============================================================
// 1) prep: Kahan A per row; codebook bf16 2-way split planes + double B
// ============================================================
__global__ void prep_kernel(const float* __restrict__ x, const float* __restrict__ cb) {
    const int b = blockIdx.x, t = threadIdx.x;
    if (b < 512) {
        const int row = b * 128 + t;
        const float4* xr = (const float4*)(x + (size_t)row * DIM);
        float s = 0.f, comp = 0.f;
        #pragma unroll 4
        for (int i = 0; i < DIM / 4; i++) {
            float4 v = xr[i];
            float e[4] = {v.x, v.y, v.z, v.w};
            #pragma unroll
            for (int j = 0; j < 4; j++) {       // exact R11 Kahan sequence
                float tm = __fmul_rn(e[j], e[j]);
                float y  = __fsub_rn(tm, comp);
                float u  = __fadd_rn(s, y);
                comp     = __fsub_rn(__fsub_rn(u, s), y);
                s        = u;
            }
        }
        g_A[row] = s;
    } else {
        const int code = (b - 512) * 128 + t;   // 8 blocks x 128
        const float4* cr = (const float4*)(cb + (size_t)code * DIM);
        uint2* p0 = (uint2*)(g_c0 + (size_t)code * DIM);
        uint2* p1 = (uint2*)(g_c1 + (size_t)code * DIM);
        double sd = 0.0;
        #pragma unroll 4
        for (int i = 0; i < DIM / 4; i++) {
            float4 v = cr[i];
            float e[4] = {v.x, v.y, v.z, v.w};
            __nv_bfloat16 a[4], bb[4];
            #pragma unroll
            for (int j = 0; j < 4; j++) {
                split2(e[j], a[j], bb[j]);
                sd += (double)__fmul_rn(e[j], e[j]);
            }
            p0[i] = uint2{pkbf(a[0], a[1]), pkbf(a[2], a[3])};
            p1[i] = uint2{pkbf(bb[0], bb[1]), pkbf(bb[2], bb[3])};
        }
        g_bsq[code] = (float)sd;
        g_counts[code] = 0;
        if (b == 512 && t == 0) g_nres = 0;
    }
}

// ============================================================
// 2) mma_main: K=384 bf16 HMMA candidate gen + top-2 margin flags
// ============================================================
#define SMA  0
#define SMC  (128 * XS * 2)                 // 100352
#define SMBS (SMC + KC * XS * 2)            // +50176 = 150528
#define SMT  (SMBS + 256)                   // 150784 bytes

__global__ __launch_bounds__(256)
void mma_main(const float* __restrict__ x) {
    extern __shared__ char smem[];
    const uint32_t sb = smem_u32(smem);
    char* xab = smem + SMA;                  // bf16[128][XS]
    char* csb = smem + SMC;                  // bf16[KC][XS]
    float* bs = (float*)(smem + SMBS);

    const int t = threadIdx.x;
    const int w = t >> 5, l = t & 31;
    const int g = l >> 2, tig = l & 3;
    const int base = blockIdx.x * 128;

    // ---- stage A: load x fp32, split inline to [x0 | x0 | x1]
    {
        const float4* x4 = (const float4*)(x + (size_t)base * DIM);
        #pragma unroll
        for (int j = 0; j < 16; j++) {
            int idx = t + 256 * j;
            int row = idx >> 5, q = idx & 31;
            float4 v = x4[idx];
            float e[4] = {v.x, v.y, v.z, v.w};
            __nv_bfloat16 a[4], b[4];
            #pragma unroll
            for (int i = 0; i < 4; i++) split2(e[i], a[i], b[i]);
            uint2 u0 = {pkbf(a[0], a[1]), pkbf(a[2], a[3])};
            uint2 u1 = {pkbf(b[0], b[1]), pkbf(b[2], b[3])};
            char* rp = xab + (row * XS + 4 * q) * 2;
            *(uint2*)(rp)       = u0;        // x0 at k
            *(uint2*)(rp + 256) = u0;        // x0 dup at k+128
            *(uint2*)(rp + 512) = u1;        // x1 at k+256
        }
    }

    const float A0 = g_A[base + 16 * w + g];
    const float A1 = g_A[base + 16 * w + g + 8];

    // ldmatrix lane addresses
    const uint32_t aaddr = sb + SMA + (uint32_t)(((16 * w + (l & 15)) * XS + (l >> 4) * 8) * 2);
    const uint32_t baddr = sb + SMC + (uint32_t)((((l & 7) * XS) + ((l >> 3) & 1) * 8) * 2);

    float v1[2] = {INFINITY, INFINITY}, v2[2] = {INFINITY, INFINITY};
    int   i1[2] = {0, 0},               i2[2] = {0, 0};

    for (int kt = 0; kt < NTILES; kt++) {
        __syncthreads();
        // ---- stage C tile: [c0 | c1 | c0] per code
        {
            const uint4* s0 = (const uint4*)(g_c0 + (size_t)kt * KC * DIM);
            const uint4* s1 = (const uint4*)(g_c1 + (size_t)kt * KC * DIM);
            #pragma unroll
            for (int j = 0; j < 4; j++) {
                int idx = t + 256 * j;           // 1024 uint4 (16 per code)
                int code = idx >> 4, q = idx & 15;
                uint4 a = s0[idx];
                uint4 b = s1[idx];
                char* rp = csb + (code * XS) * 2 + q * 16;
                *(uint4*)(rp)       = a;         // c0
                *(uint4*)(rp + 512) = a;         // c0 dup at k+256
                *(uint4*)(rp + 256) = b;         // c1 at k+128
            }
            if (t < KC) bs[t] = g_bsq[kt * KC + t];
        }
        __syncthreads();

        float acc[8][4];
        #pragma unroll
        for (int nb = 0; nb < 8; nb++)
            #pragma unroll
            for (int c = 0; c < 4; c++) acc[nb][c] = 0.f;

        #pragma unroll 1
        for (int ks = 0; ks < KEXT / 16; ks++) {       // 24
            uint32_t a0, a1, a2, a3;
            asm volatile("ldmatrix.sync.aligned.m8n8.x4.shared.b16 {%0,%1,%2,%3}, [%4];"
                : "=r"(a0), "=r"(a1), "=r"(a2), "=r"(a3) : "r"(aaddr + ks * 32));
            #pragma unroll
            for (int nb = 0; nb < 8; nb++) {
                uint32_t b0, b1;
                asm volatile("ldmatrix.sync.aligned.m8n8.x2.shared.b16 {%0,%1}, [%2];"
                    : "=r"(b0), "=r"(b1) : "r"(baddr + nb * (8 * XS * 2) + ks * 32));
                asm volatile(
                    "mma.sync.aligned.m16n8k16.row.col.f32.bf16.bf16.f32 "
                    "{%0,%1,%2,%3}, {%4,%5,%6,%7}, {%8,%9}, {%0,%1,%2,%3};"
                    : "+f"(acc[nb][0]), "+f"(acc[nb][1]), "+f"(acc[nb][2]), "+f"(acc[nb][3])
                    : "r"(a0), "r"(a1), "r"(a2), "r"(a3), "r"(b0), "r"(b1));
            }
        }

        // ---- drain: d = fl( fl(A+B) - 2*dot ), top-2 per row
        #pragma unroll
        for (int nb = 0; nb < 8; nb++) {
            int c0i = kt * KC + nb * 8 + 2 * tig;
            float B0 = bs[nb * 8 + 2 * tig], B1 = bs[nb * 8 + 2 * tig + 1];
            float d00 = __fmaf_rn(acc[nb][0], -2.0f, __fadd_rn(A0, B0));
            float d01 = __fmaf_rn(acc[nb][1], -2.0f, __fadd_rn(A0, B1));
            float d10 = __fmaf_rn(acc[nb][2], -2.0f, __fadd_rn(A1, B0));
            float d11 = __fmaf_rn(acc[nb][3], -2.0f, __fadd_rn(A1, B1));
            #define T2(s, d, ix) do {                                          \
                if (d < v1[s] || (d == v1[s] && (ix) < i1[s])) {               \
                    v2[s] = v1[s]; i2[s] = i1[s]; v1[s] = d; i1[s] = (ix);     \
                } else if (d < v2[s] || (d == v2[s] && (ix) < i2[s])) {        \
                    v2[s] = d; i2[s] = (ix);                                   \
                } } while (0)
            T2(0, d00, c0i); T2(0, d01, c0i + 1);
            T2(1, d10, c0i); T2(1, d11, c0i + 1);
            #undef T2
        }
    }

    // ---- quad-lane lexicographic top-2 merge (tig dimension)
    #pragma unroll
    for (int s = 0; s < 2; s++) {
        #pragma unroll
        for (int off = 1; off <= 2; off <<= 1) {
            float ov1 = __shfl_xor_sync(0xFFFFFFFFu, v1[s], off);
            int   oi1 = __shfl_xor_sync(0xFFFFFFFFu, i1[s], off);
            float ov2 = __shfl_xor_sync(0xFFFFFFFFu, v2[s], off);
            int   oi2 = __shfl_xor_sync(0xFFFFFFFFu, i2[s], off);
            if (ov1 < v1[s] || (ov1 == v1[s] && oi1 < i1[s])) {
                float cv; int ci;
                if (v1[s] < ov2 || (v1[s] == ov2 && i1[s] < oi2)) { cv = v1[s]; ci = i1[s]; }
                else                                               { cv = ov2;  ci = oi2;  }
                v1[s] = ov1; i1[s] = oi1; v2[s] = cv; i2[s] = ci;
            } else if (ov1 < v2[s] || (ov1 == v2[s] && oi1 < i2[s])) {
                v2[s] = ov1; i2[s] = oi1;
            }
        }
    }
    if (tig == 0) {
        #pragma unroll
        for (int s = 0; s < 2; s++) {
            int row = base + 16 * w + g + 8 * s;
            g_idx[row] = i1[s];
            if (!(v2[s] > v1[s] + MARGIN)) {
                int slot = atomicAdd(&g_nres, 1);
                g_res[slot] = row;
            }
        }
    }
}

// ============================================================
// 3) rescan: exact full scalar scan (R11 numerics) for flagged rows
// ============================================================
__global__ void rescan_kernel(const float* __restrict__ x, const float* __restrict__ cb) {
    __shared__ float xr[DIM];
    __shared__ float rv[256];
    __shared__ int   ri[256];
    const int t = threadIdx.x;
    const int nres = g_nres;

    for (int wi = blockIdx.x; wi < nres; wi += gridDim.x) {
        const int row = g_res[wi];
        if (t < 32) {
            float4 v = ((const float4*)(x + (size_t)row * DIM))[t];
            xr[4 * t] = v.x; xr[4 * t + 1] = v.y; xr[4 * t + 2] = v.z; xr[4 * t + 3] = v.w;
        }
        __syncthreads();
        const float A = g_A[row];

        float bv = INFINITY; int bi = 0;
        #pragma unroll 1
        for (int j = 0; j < 4; j++) {
            const int code = t * 4 + j;
            const float* cr = cb + (size_t)code * DIM;
            float acc = 0.f;
            #pragma unroll 8
            for (int k = 0; k < DIM; k++)             // sequential ascending chain
                acc = __fmaf_rn(xr[k], cr[k], acc);
            float d = __fadd_rn(__fadd_rn(A, g_bsq[code]), -(2.0f * acc));
            if (d < bv || (d == bv && code < bi)) { bv = d; bi = code; }
        }
        rv[t] = bv; ri[t] = bi;
        __syncthreads();
        for (int s = 128; s > 0; s >>= 1) {
            if (t < s) {
                float ov = rv[t + s]; int oi = ri[t + s];
                if (ov < rv[t] || (ov == rv[t] && oi < ri[t])) { rv[t] = ov; ri[t] = oi; }
            }
            __syncthreads();
        }
        if (t == 0) g_idx[row] = ri[0];
        __syncthreads();
    }
}

// ============================================================
// 4) epilogue: quantized + encodings + loss partials + counts
// ============================================================
#define XSTRIDE 132
#define EP_X    0
#define EP_SIDX (128 * XSTRIDE * 4)
#define EP_RED  (EP_SIDX + 512)
#define EP_TOT  (EP_RED + 1024)

__global__ __launch_bounds__(256)
void epi_kernel(const float* __restrict__ x, const float* __restrict__ cb,
                float* __restrict__ outq, float* __restrict__ oute) {
    extern __shared__ char esm[];
    float* xst  = (float*)(esm + EP_X);
    int*   sidx = (int*)(esm + EP_SIDX);
    float* red  = (float*)(esm + EP_RED);
    const int t = threadIdx.x;
    const int base = blockIdx.x * 128;

    {
        const float4* x4 = (const float4*)(x + (size_t)base * DIM);
        #pragma unroll
        for (int j = 0; j < 16; j++) {
            int idx = t + 256 * j;
            int row = idx >> 5, q = idx & 31;
            float4 v = x4[idx];
            float* d = xst + row * XSTRIDE + q * 4;
            d[0] = v.x; d[1] = v.y; d[2] = v.z; d[3] = v.w;
        }
    }
    if (t < 128) {
        int c = g_idx[base + t];
        sidx[t] = c;
        atomicAdd(&g_counts[c], 1);
    }
    __syncthreads();

    float lsum = 0.f;
    {
        const int row = t >> 1, half = t & 1;
        const int code = sidx[row];
        const float4* q4 = (const float4*)(cb + (size_t)code * DIM + half * 64);
        const float*  xs = xst + row * XSTRIDE + half * 64;
        float* qo = outq + (size_t)(base + row) * DIM + half * 64;
        #pragma unroll 4
        for (int i = 0; i < 16; i++) {
            float4 q = q4[i];
            float d0 = q.x - xs[4*i],   d1 = q.y - xs[4*i+1];
            float d2 = q.z - xs[4*i+2], d3 = q.w - xs[4*i+3];
            lsum += d0 * d0 + d1 * d1 + d2 * d2 + d3 * d3;
            qo[4*i] = q.x; qo[4*i+1] = q.y; qo[4*i+2] = q.z; qo[4*i+3] = q.w;
        }
    }
    red[t] = lsum;
    __syncthreads();
    for (int s = 128; s > 0; s >>= 1) {
        if (t < s) red[t] += red[t + s];
        __syncthreads();
    }
    if (t == 0) g_bloss[blockIdx.x] = red[0];

    for (int r2 = 0; r2 < 128; r2++) {
        int idx = sidx[r2];
        float2* erow = (float2*)(oute + (size_t)(base + r2) * KCODES);
        int pa = 2 * t, pb = 2 * (t + 256);
        float2 va, vb;
        va.x = (pa     == idx) ? 1.f : 0.f;
        va.y = (pa + 1 == idx) ? 1.f : 0.f;
        vb.x = (pb     == idx) ? 1.f : 0.f;
        vb.y = (pb + 1 == idx) ? 1.f : 0.f;
        erow[t] = va;
        erow[t + 256] = vb;
    }
}

// ============================================================
// 5) finalize
// ============================================================
__global__ void fin_kernel(float* __restrict__ out_loss, float* __restrict__ out_perp) {
    __shared__ float sh[1024];
    const int t = threadIdx.x;

    float c = (float)g_counts[t];
    float p = c * (1.0f / (float)N_PTS);
    sh[t] = p * logf(p + 1e-10f);
    __syncthreads();
    for (int s = 512; s > 0; s >>= 1) {
        if (t < s) sh[t] += sh[t + s];
        __syncthreads();
    }
    float ent = sh[0];
    __syncthreads();

    sh[t] = (t < 512) ? g_bloss[t] : 0.f;
    __syncthreads();
    for (int s = 512; s > 0; s >>= 1) {
        if (t < s) sh[t] += sh[t + s];
        __syncthreads();
    }
    if (t == 0) {
        *out_perp = expf(-ent);
        *out_loss = 1.25f * sh[0] / (float)((size_t)N_PTS * DIM);
    }
}

// ============================================================
// launch
// ============================================================
extern "C" void kernel_launch(void* const* d_in, const int* in_sizes, int n_in,
                              void* d_out, int out_size) {
    const float* x  = (const float*)d_in[0];   // [65536, 128] f32
    const float* cb = (const float*)d_in[1];   // [1024, 128]  f32
    float* out  = (float*)d_out;
    float* outq = out + 1;
    float* outp = out + 1 + (size_t)N_PTS * DIM;
    float* oute = outp + 1;

    static int attr_done = 0;
    if (!attr_done) {
        cudaFuncSetAttribute(mma_main, cudaFuncAttributeMaxDynamicSharedMemorySize, SMT);
        cudaFuncSetAttribute(epi_kernel, cudaFuncAttributeMaxDynamicSharedMemorySize, EP_TOT);
        attr_done = 1;
    }

    prep_kernel<<<520, 128>>>(x, cb);
    mma_main<<<512, 256, SMT>>>(x);
    rescan_kernel<<<2048, 256>>>(x, cb);
    epi_kernel<<<512, 256, EP_TOT>>>(x, cb, outq, oute);
    fin_kernel<<<1, 1024>>>(out, outp);
}

// round 16
// speedup vs baseline: 1.8107x; 1.8107x over previous
#include <cuda_runtime.h>
#include <cstdint>
#include <math.h>

#define N_PTS    65536
#define DIM      128
#define KCODES   1024
#define KC       64              // codes per smem tile
#define NTILES   (KCODES / KC)   // 16
#define CJ       8               // codes per thread (= per warp group)
#define ROWS_CTA 64
#define PAIRS    32
#define THREADS  256
#define NCTAS    (N_PTS / ROWS_CTA)   // 1024

typedef unsigned long long ull;

// ---- f32x2 packed math (sm_103a); lanes are IEEE fp32 fma.rn ----
__device__ __forceinline__ ull dup2(float a) {
    ull r; asm("mov.b64 %0, {%1, %1};" : "=l"(r) : "f"(a)); return r;
}
__device__ __forceinline__ void unpack2(ull v, float& a, float& b) {
    asm("mov.b64 {%0, %1}, %2;" : "=f"(a), "=f"(b) : "l"(v));
}
__device__ __forceinline__ ull fma2(ull a, ull b, ull c) {
    ull d; asm("fma.rn.f32x2 %0, %1, %2, %3;" : "=l"(d) : "l"(a), "l"(b), "l"(c)); return d;
}

// ---- device scratch ----
__device__ float g_bsq[KCODES];
__device__ int   g_counts[KCODES];
__device__ float g_bloss[NCTAS];

// smem layout (bytes)
#define SM_XS    0                       // ull  xs[128 k][32 pair] = 32768
#define SM_CS    32768                   // ull  csd[KC][128 k] dup'd = 65536
#define SM_BS    98304                   // f32  bs[KC]  = 256
#define SM_A     98560                   // f32  sA[64]  = 256
#define SM_TOTAL 98816
// overlays on CS region, used only after the mainloop (barrier-separated):
#define SM_SD    SM_CS                   // f32 sd[8][64] = 2048
#define SM_SI    (SM_CS + 2048)          // int si[8][64] = 2048
#define SM_SIDX  (SM_CS + 4096)          // int sidx[64]  = 256
#define SM_RED   (SM_CS + 4352)          // f32 red[256]  = 1024

// ============================================================
// 1) B_k = fl( double-accumulated sum of fl(c^2) ) + zero counts
// ============================================================
__global__ void prep_kernel(const float* __restrict__ cb) {
    __shared__ float sc[8][DIM];
    const int t = threadIdx.x;
    const int b = blockIdx.x;

    const float4* c4 = (const float4*)(cb + (size_t)b * 8 * DIM);
    #pragma unroll
    for (int i = 0; i < 2; i++) {
        int idx  = t + 128 * i;
        int row  = idx >> 5;
        int posq = idx & 31;
        float4 v = c4[idx];
        sc[row][posq * 4 + 0] = v.x;
        sc[row][posq * 4 + 1] = v.y;
        sc[row][posq * 4 + 2] = v.z;
        sc[row][posq * 4 + 3] = v.w;
    }
    __syncthreads();

    if (t < 8) {
        double s = 0.0;
        #pragma unroll 8
        for (int k = 0; k < DIM; k++) {
            float q = __fmul_rn(sc[t][k], sc[t][k]);
            s += (double)q;
        }
        g_bsq[b * 8 + t] = (float)s;
    }
    if (b < 8) g_counts[b * 128 + t] = 0;
}

// ============================================================
// 2) Main: 64-row blocks, 2 CTAs/SM, pair=lane / codegroup=warp,
//    register-prefetched code tiles, bit-faithful fp32 chains.
// ============================================================
__global__ __launch_bounds__(THREADS, 2)
void vq_main(const float* __restrict__ x, const float* __restrict__ cb,
             float* __restrict__ outq, float* __restrict__ oute) {
    extern __shared__ char smem[];
    ull*    xs   = (ull*)(smem + SM_XS);     // [k*32 + pair]; lane0=row p, lane1=row p+32
    float*  xsf  = (float*)(smem + SM_XS);
    ull*    csd  = (ull*)(smem + SM_CS);     // [code*128 + k], (c,c) duplicated
    float*  bs   = (float*)(smem + SM_BS);
    float*  sA   = (float*)(smem + SM_A);
    float*  sd   = (float*)(smem + SM_SD);
    int*    si   = (int*)(smem + SM_SI);
    int*    sidx = (int*)(smem + SM_SIDX);
    float*  red  = (float*)(smem + SM_RED);

    const int t    = threadIdx.x;
    const int l    = t & 31;      // lane = pair index (rows l, l+32)
    const int w    = t >> 5;      // warp = code group (codes w*8 .. w*8+7)
    const int base = blockIdx.x * ROWS_CTA;

    // ---- stage x pair-packed: lane0 = row base+p, lane1 = row base+32+p
    {
        const float4* x4 = (const float4*)(x + (size_t)base * DIM);
        #pragma unroll
        for (int i = 0; i < (ROWS_CTA * DIM / 4) / THREADS; i++) {   // 8
            int idx  = t + THREADS * i;
            int row  = idx >> 5;
            int posq = idx & 31;
            float4 v = x4[idx];
            int pr = row & 31, ln = row >> 5, k0 = posq * 4;
            xsf[((k0 + 0) * PAIRS + pr) * 2 + ln] = v.x;
            xsf[((k0 + 1) * PAIRS + pr) * 2 + ln] = v.y;
            xsf[((k0 + 2) * PAIRS + pr) * 2 + ln] = v.z;
            xsf[((k0 + 3) * PAIRS + pr) * 2 + ln] = v.w;
        }
    }
    __syncthreads();

    // ---- A = Kahan fp32 sum of fl(x^2) (R11-proven exact sequence)
    if (t < ROWS_CTA) {
        const int pr = t & 31, ln = t >> 5;
        float s = 0.f, comp = 0.f;
        #pragma unroll 4
        for (int k = 0; k < DIM; k++) {
            float v  = xsf[(k * PAIRS + pr) * 2 + ln];
            float tm = __fmul_rn(v, v);
            float y  = __fsub_rn(tm, comp);
            float u  = __fadd_rn(s, y);
            comp     = __fsub_rn(__fsub_rn(u, s), y);
            s        = u;
        }
        sA[t] = s;
    }
    __syncthreads();

    const float A0 = sA[l];
    const float A1 = sA[l + 32];

    float best0 = INFINITY, best1 = INFINITY;
    int   bi0 = 0, bi1 = 0;

    // ---- prologue: prefetch tile 0 codes into registers
    float4 pf[8];
    {
        const float4* c4 = (const float4*)cb;
        #pragma unroll
        for (int j = 0; j < 8; j++) pf[j] = c4[t + THREADS * j];   // 2048 float4/tile
    }

    for (int kt = 0; kt < NTILES; kt++) {
        __syncthreads();   // previous tile's reads complete
        // ---- store prefetched tile (duplicated (c,c)), then prefetch next
        {
            #pragma unroll
            for (int j = 0; j < 8; j++) {
                int idx  = t + THREADS * j;
                int code = idx >> 5;
                int posq = idx & 31;
                float4 v = pf[j];
                ulonglong2* dst = (ulonglong2*)(csd + code * DIM + posq * 4);
                ulonglong2 w0, w1;
                w0.x = dup2(v.x); w0.y = dup2(v.y);
                w1.x = dup2(v.z); w1.y = dup2(v.w);
                dst[0] = w0; dst[1] = w1;
            }
            if (t < KC) bs[t] = g_bsq[kt * KC + t];
        }
        if (kt + 1 < NTILES) {
            const float4* c4 = (const float4*)(cb + (size_t)(kt + 1) * KC * DIM);
            #pragma unroll
            for (int j = 0; j < 8; j++) pf[j] = c4[t + THREADS * j];
        }
        __syncthreads();

        ull acc[CJ];
        #pragma unroll
        for (int c = 0; c < CJ; c++) acc[c] = 0ull;

        const ull* cdup = csd + (w * CJ) * DIM;   // warp-uniform base

        #pragma unroll 2
        for (int kk = 0; kk < DIM / 2; kk++) {
            ull xa = xs[(2 * kk) * PAIRS + l];        // k = 2kk,  rows (l, l+32)
            ull xb = xs[(2 * kk + 1) * PAIRS + l];    // k = 2kk+1
            #pragma unroll
            for (int c = 0; c < CJ; c++) {
                ulonglong2 cc = *(const ulonglong2*)(cdup + c * DIM + 2 * kk);
                acc[c] = fma2(xa, cc.x, acc[c]);      // ascending k per chain
                acc[c] = fma2(xb, cc.y, acc[c]);
            }
        }

        // d = fl( fl(A + B) - 2*dot ) — reference's exact fp32 formula
        #pragma unroll
        for (int c = 0; c < CJ; c++) {
            float B    = bs[w * CJ + c];
            int   gidx = kt * KC + w * CJ + c;
            float f0, f1;
            unpack2(acc[c], f0, f1);
            float dd0 = __fadd_rn(__fadd_rn(A0, B), -(2.0f * f0));
            float dd1 = __fadd_rn(__fadd_rn(A1, B), -(2.0f * f1));
            if (dd0 < best0) { best0 = dd0; bi0 = gidx; }
            if (dd1 < best1) { best1 = dd1; bi1 = gidx; }
        }
    }

    __syncthreads();   // mainloop done; safe to overlay cs region

    sd[w * ROWS_CTA + l]      = best0;  si[w * ROWS_CTA + l]      = bi0;
    sd[w * ROWS_CTA + l + 32] = best1;  si[w * ROWS_CTA + l + 32] = bi1;
    __syncthreads();

    // lexicographic (d, idx) reduction over the 8 code groups
    if (t < ROWS_CTA) {
        float bd = sd[t];  int bi = si[t];
        #pragma unroll
        for (int g = 1; g < 8; g++) {
            float od = sd[g * ROWS_CTA + t]; int oi = si[g * ROWS_CTA + t];
            if (od < bd || (od == bd && oi < bi)) { bd = od; bi = oi; }
        }
        sidx[t] = bi;
        atomicAdd(&g_counts[bi], 1);
    }
    __syncthreads();

    // ---- quantized + loss: 4 threads per row (quarter-row each)
    float lsum = 0.f;
    {
        const int row = t >> 2, qq = t & 3;
        const int code = sidx[row];
        const int pr = row & 31, ln = row >> 5;
        const float4* q4 = (const float4*)(cb + (size_t)code * DIM + qq * 32);
        float* qo = outq + (size_t)(base + row) * DIM + qq * 32;   // 4B-aligned only
        #pragma unroll
        for (int i = 0; i < 8; i++) {
            float4 q = q4[i];
            int k0 = qq * 32 + 4 * i;
            float xa = xsf[((k0 + 0) * PAIRS + pr) * 2 + ln];
            float xb = xsf[((k0 + 1) * PAIRS + pr) * 2 + ln];
            float xc = xsf[((k0 + 2) * PAIRS + pr) * 2 + ln];
            float xd = xsf[((k0 + 3) * PAIRS + pr) * 2 + ln];
            float d0 = q.x - xa, d1 = q.y - xb, d2 = q.z - xc, d3 = q.w - xd;
            lsum += d0 * d0 + d1 * d1 + d2 * d2 + d3 * d3;
            qo[4 * i + 0] = q.x; qo[4 * i + 1] = q.y;
            qo[4 * i + 2] = q.z; qo[4 * i + 3] = q.w;
        }
    }

    __syncthreads();
    red[t] = lsum;
    __syncthreads();
    for (int s = 128; s > 0; s >>= 1) {
        if (t < s) red[t] += red[t + s];
        __syncthreads();
    }
    if (t == 0) g_bloss[blockIdx.x] = red[0];

    // ---- fused encodings: cooperative coalesced one-hot rows
    for (int r2 = 0; r2 < ROWS_CTA; r2++) {
        int idx = sidx[r2];
        float2* erow = (float2*)(oute + (size_t)(base + r2) * KCODES);
        int pa = 2 * t, pb = 2 * (t + 256);
        float2 va, vb;
        va.x = (pa     == idx) ? 1.f : 0.f;
        va.y = (pa + 1 == idx) ? 1.f : 0.f;
        vb.x = (pb     == idx) ? 1.f : 0.f;
        vb.y = (pb + 1 == idx) ? 1.f : 0.f;
        erow[t] = va;
        erow[t + 256] = vb;
    }
}

// ============================================================
// 3) Finalize: loss + perplexity scalars
// ============================================================
__global__ void fin_kernel(float* __restrict__ out_loss,
                           float* __restrict__ out_perp) {
    __shared__ float sh[1024];
    const int t = threadIdx.x;

    float c = (float)g_counts[t];
    float p = c * (1.0f / (float)N_PTS);
    sh[t] = p * logf(p + 1e-10f);
    __syncthreads();
    for (int s = 512; s > 0; s >>= 1) {
        if (t < s) sh[t] += sh[t + s];
        __syncthreads();
    }
    float ent = sh[0];
    __syncthreads();

    sh[t] = g_bloss[t];          // NCTAS == 1024
    __syncthreads();
    for (int s = 512; s > 0; s >>= 1) {
        if (t < s) sh[t] += sh[t + s];
        __syncthreads();
    }
    if (t == 0) {
        *out_perp = expf(-ent);
        *out_loss = 1.25f * sh[0] / (float)((size_t)N_PTS * DIM);
    }
}

// ============================================================
// launch
// ============================================================
extern "C" void kernel_launch(void* const* d_in, const int* in_sizes, int n_in,
                              void* d_out, int out_size) {
    const float* x  = (const float*)d_in[0];   // [65536, 128] f32
    const float* cb = (const float*)d_in[1];   // [1024, 128]  f32
    float* out  = (float*)d_out;
    float* outq = out + 1;
    float* outp = out + 1 + (size_t)N_PTS * DIM;
    float* oute = outp + 1;

    static int attr_done = 0;
    if (!attr_done) {
        cudaFuncSetAttribute(vq_main, cudaFuncAttributeMaxDynamicSharedMemorySize,
                             SM_TOTAL);
        attr_done = 1;
    }

    prep_kernel<<<KCODES / 8, 128>>>(cb);
    vq_main<<<NCTAS, THREADS, SM_TOTAL>>>(x, cb, outq, oute);
    fin_kernel<<<1, 1024>>>(out, outp);
}

// round 17
// speedup vs baseline: 2.3143x; 1.2781x over previous
#include <cuda_runtime.h>
#include <cstdint>
#include <math.h>

#define N_PTS    65536
#define DIM      128
#define KCODES   1024
#define KC       64              // codes per smem tile
#define NTILES   (KCODES / KC)   // 16
#define CJ       8               // codes per thread per tile (warp-uniform group)
#define RP       4               // row-pairs per thread
#define ROWS_CTA 256
#define PAIRS    128
#define THREADS  256
#define NCTAS    (N_PTS / ROWS_CTA)   // 256

typedef unsigned long long ull;

// ---- f32x2 packed math (sm_103a); lanes are IEEE fp32 fma.rn ----
__device__ __forceinline__ ull dup2(float a) {
    ull r; asm("mov.b64 %0, {%1, %1};" : "=l"(r) : "f"(a)); return r;
}
__device__ __forceinline__ void unpack2(ull v, float& a, float& b) {
    asm("mov.b64 {%0, %1}, %2;" : "=f"(a), "=f"(b) : "l"(v));
}
__device__ __forceinline__ ull fma2(ull a, ull b, ull c) {
    ull d; asm("fma.rn.f32x2 %0, %1, %2, %3;" : "=l"(d) : "l"(a), "l"(b), "l"(c)); return d;
}

// ---- device scratch ----
__device__ float g_bsq[KCODES];
__device__ int   g_counts[KCODES];
__device__ float g_bloss[NCTAS];

// smem layout (bytes)
#define SM_XS    0                      // ull  xs[128 k][128 pair] = 131072
#define SM_CS    131072                 // ull  csd[KC][128 k] dup'd = 65536
#define SM_BS    196608                 // f32  bs[KC]               = 256
#define SM_A     196864                 // f32  sA[256 rows]         = 1024
#define SM_TOTAL 197888
// overlays on CS region, used only after the mainloop (barrier-separated):
#define SM_SD    SM_CS                  // f32 sd[8][256]  = 8192
#define SM_SI    (SM_CS + 8192)         // int si[8][256]  = 8192
#define SM_SIDX  (SM_CS + 16384)        // int sidx[256]   = 1024
#define SM_RED   (SM_CS + 17408)        // f32 red[256]    = 1024

// encodings zero-fill: float2 per CTA slab, split across tiles
#define ENC_F2_TILE 8192                // (ROWS_CTA*KCODES/2)/NTILES

// ============================================================
// 1) B_k = fl( double-accumulated sum of fl(c^2) ), coalesced staging
// ============================================================
__global__ void prep_kernel(const float* __restrict__ cb) {
    __shared__ float sc[8][DIM];
    const int t = threadIdx.x;
    const int b = blockIdx.x;

    const float4* c4 = (const float4*)(cb + (size_t)b * 8 * DIM);
    #pragma unroll
    for (int i = 0; i < 2; i++) {
        int idx  = t + 128 * i;
        int row  = idx >> 5;
        int posq = idx & 31;
        float4 v = c4[idx];
        sc[row][posq * 4 + 0] = v.x;
        sc[row][posq * 4 + 1] = v.y;
        sc[row][posq * 4 + 2] = v.z;
        sc[row][posq * 4 + 3] = v.w;
    }
    __syncthreads();

    if (t < 8) {
        double s = 0.0;
        #pragma unroll 8
        for (int k = 0; k < DIM; k++) {
            float q = __fmul_rn(sc[t][k], sc[t][k]);
            s += (double)q;
        }
        g_bsq[b * 8 + t] = (float)s;
    }
    if (b < 8) g_counts[b * 128 + t] = 0;
}

// ============================================================
// 2) Main: R11 structure (proven 631us) + overlapped encodings zero-fill
// ============================================================
__global__ __launch_bounds__(THREADS)
void vq_main(const float* __restrict__ x, const float* __restrict__ cb,
             float* __restrict__ outq, float* __restrict__ oute) {
    extern __shared__ char smem[];
    ull*    xs   = (ull*)(smem + SM_XS);     // [k*128 + pair]; lanes = rows (p, p+128)
    float*  xsf  = (float*)(smem + SM_XS);   // scalar view
    ull*    csd  = (ull*)(smem + SM_CS);     // [code*128 + k], (c,c) duplicated
    float*  bs   = (float*)(smem + SM_BS);
    float*  sA   = (float*)(smem + SM_A);
    float*  sd   = (float*)(smem + SM_SD);
    int*    si   = (int*)(smem + SM_SI);
    int*    sidx = (int*)(smem + SM_SIDX);
    float*  red  = (float*)(smem + SM_RED);

    const int t    = threadIdx.x;
    const int pg   = t & 31;      // lane: pair group
    const int cg   = t >> 5;      // warp-uniform: code group (codes cg*8..cg*8+7)
    const int base = blockIdx.x * ROWS_CTA;

    // thread's 4 pairs: two vector-adjacent duos
    int P[RP];
    P[0] = 2 * pg;      P[1] = 2 * pg + 1;
    P[2] = 2 * pg + 64; P[3] = 2 * pg + 65;

    // ---- stage x pair-packed: lane0 = row base+pr, lane1 = row base+128+pr
    {
        const float4* x4 = (const float4*)(x + (size_t)base * DIM);
        #pragma unroll
        for (int i = 0; i < (ROWS_CTA * DIM / 4) / THREADS; i++) {   // 32
            int idx  = t + THREADS * i;
            int row  = idx >> 5;
            int posq = idx & 31;
            float4 v = x4[idx];
            int pr = row & 127, ln = row >> 7, k0 = posq * 4;
            xsf[((k0 + 0) * PAIRS + pr) * 2 + ln] = v.x;
            xsf[((k0 + 1) * PAIRS + pr) * 2 + ln] = v.y;
            xsf[((k0 + 2) * PAIRS + pr) * 2 + ln] = v.z;
            xsf[((k0 + 3) * PAIRS + pr) * 2 + ln] = v.w;
        }
    }
    __syncthreads();

    // ---- A = Kahan fp32 sum of fl(x^2), one thread per row (R9/R11-validated)
    {
        const int pr = t & 127, ln = t >> 7;
        float s = 0.f, comp = 0.f;
        #pragma unroll 4
        for (int k = 0; k < DIM; k++) {
            float v  = xsf[(k * PAIRS + pr) * 2 + ln];
            float tm = __fmul_rn(v, v);
            float y  = __fsub_rn(tm, comp);
            float u  = __fadd_rn(s, y);
            comp     = __fsub_rn(__fsub_rn(u, s), y);
            s        = u;
        }
        sA[t] = s;
    }
    __syncthreads();

    float A0[RP], A1[RP];
    #pragma unroll
    for (int r = 0; r < RP; r++) { A0[r] = sA[P[r]]; A1[r] = sA[P[r] + 128]; }

    float best0[RP], best1[RP];
    int   bi0[RP],   bi1[RP];
    #pragma unroll
    for (int r = 0; r < RP; r++) {
        best0[r] = INFINITY; best1[r] = INFINITY; bi0[r] = 0; bi1[r] = 0;
    }

    float2* encz = (float2*)(oute + (size_t)base * KCODES);

    for (int kt = 0; kt < NTILES; kt++) {
        __syncthreads();
        // stage KC codes duplicated (c,c): csd[code][k]
        {
            const float4* c4 = (const float4*)(cb + (size_t)kt * KC * DIM);
            #pragma unroll
            for (int i = 0; i < (KC * DIM / 4) / THREADS; i++) {     // 8
                int idx  = t + THREADS * i;
                int code = idx >> 5;
                int posq = idx & 31;
                float4 v = c4[idx];
                ulonglong2* dst = (ulonglong2*)(csd + code * DIM + posq * 4);
                ulonglong2 w0, w1;
                w0.x = dup2(v.x); w0.y = dup2(v.y);
                w1.x = dup2(v.z); w1.y = dup2(v.w);
                dst[0] = w0; dst[1] = w1;
            }
            if (t < KC) bs[t] = g_bsq[kt * KC + t];
        }
        __syncthreads();

        // ---- overlapped encodings zero-fill: 1/NTILES of the slab per tile.
        // Coalesced STG.64; DRAM time hides under the fma mainloop.
        {
            const float2 z2 = {0.f, 0.f};
            int off = kt * ENC_F2_TILE + t;
            #pragma unroll
            for (int j = 0; j < ENC_F2_TILE / THREADS; j++)          // 32
                encz[off + THREADS * j] = z2;
        }

        ull acc[RP][CJ];
        #pragma unroll
        for (int r = 0; r < RP; r++)
            #pragma unroll
            for (int c = 0; c < CJ; c++) acc[r][c] = 0ull;

        const ull* cdup = csd + (cg * CJ) * DIM;   // warp-uniform base

        #pragma unroll 2
        for (int kk = 0; kk < DIM / 2; kk++) {
            const ull* xr0 = xs + (2 * kk) * PAIRS + 2 * pg;
            ulonglong2 a0 = *(const ulonglong2*)(xr0);          // k=2kk,   pairs 2pg,2pg+1
            ulonglong2 a1 = *(const ulonglong2*)(xr0 + 64);     // k=2kk,   pairs +64,+65
            ulonglong2 b0 = *(const ulonglong2*)(xr0 + PAIRS);  // k=2kk+1
            ulonglong2 b1 = *(const ulonglong2*)(xr0 + PAIRS + 64);
            #pragma unroll
            for (int c = 0; c < CJ; c++) {
                ulonglong2 cc = *(const ulonglong2*)(cdup + c * DIM + 2 * kk);
                // ascending k per (r,c) chain: k=2kk then k=2kk+1
                acc[0][c] = fma2(a0.x, cc.x, acc[0][c]);
                acc[1][c] = fma2(a0.y, cc.x, acc[1][c]);
                acc[2][c] = fma2(a1.x, cc.x, acc[2][c]);
                acc[3][c] = fma2(a1.y, cc.x, acc[3][c]);
                acc[0][c] = fma2(b0.x, cc.y, acc[0][c]);
                acc[1][c] = fma2(b0.y, cc.y, acc[1][c]);
                acc[2][c] = fma2(b1.x, cc.y, acc[2][c]);
                acc[3][c] = fma2(b1.y, cc.y, acc[3][c]);
            }
        }

        // d = fl( fl(A + B) - 2*dot ) — reference's exact fp32 formula
        #pragma unroll
        for (int c = 0; c < CJ; c++) {
            float B    = bs[cg * CJ + c];
            int   gidx = kt * KC + cg * CJ + c;
            #pragma unroll
            for (int r = 0; r < RP; r++) {
                float f0, f1;
                unpack2(acc[r][c], f0, f1);
                float dd0 = __fadd_rn(__fadd_rn(A0[r], B), -(2.0f * f0));
                float dd1 = __fadd_rn(__fadd_rn(A1[r], B), -(2.0f * f1));
                if (dd0 < best0[r]) { best0[r] = dd0; bi0[r] = gidx; }
                if (dd1 < best1[r]) { best1[r] = dd1; bi1[r] = gidx; }
            }
        }
    }

    __syncthreads();   // mainloop + all zero-fill stores issued; overlay cs region

    #pragma unroll
    for (int r = 0; r < RP; r++) {
        sd[cg * ROWS_CTA + P[r]]       = best0[r];
        si[cg * ROWS_CTA + P[r]]       = bi0[r];
        sd[cg * ROWS_CTA + P[r] + 128] = best1[r];
        si[cg * ROWS_CTA + P[r] + 128] = bi1[r];
    }
    __syncthreads();

    // lexicographic (d, idx) reduction over the 8 code groups; 1 row/thread
    {
        float bd = sd[t];  int bi = si[t];
        #pragma unroll
        for (int g = 1; g < 8; g++) {
            float od = sd[g * ROWS_CTA + t]; int oi = si[g * ROWS_CTA + t];
            if (od < bd || (od == bd && oi < bi)) { bd = od; bi = oi; }
        }
        sidx[t] = bi;
        atomicAdd(&g_counts[bi], 1);
    }
    __syncthreads();   // sidx ready; zero-fill globally visible within CTA

    // ---- encodings patch: one float2 (holding the 1.0) per row
    {
        const int idx = sidx[t];
        float2* erow = (float2*)(oute + (size_t)(base + t) * KCODES);
        float2 v;
        v.x = (idx & 1) ? 0.f : 1.f;
        v.y = (idx & 1) ? 1.f : 0.f;
        erow[idx >> 1] = v;
    }

    // ---- quantized + loss: one row per thread
    float lsum = 0.f;
    {
        const int code = sidx[t];
        const int pr = t & 127, ln = t >> 7;
        const float4* q4 = (const float4*)(cb + (size_t)code * DIM);
        float* qo = outq + (size_t)(base + t) * DIM;   // 4B-aligned only
        #pragma unroll 4
        for (int i = 0; i < DIM / 4; i++) {
            float4 q = q4[i];
            float xa = xsf[((4 * i + 0) * PAIRS + pr) * 2 + ln];
            float xb = xsf[((4 * i + 1) * PAIRS + pr) * 2 + ln];
            float xc = xsf[((4 * i + 2) * PAIRS + pr) * 2 + ln];
            float xd = xsf[((4 * i + 3) * PAIRS + pr) * 2 + ln];
            float d0 = q.x - xa, d1 = q.y - xb, d2 = q.z - xc, d3 = q.w - xd;
            lsum += d0 * d0 + d1 * d1 + d2 * d2 + d3 * d3;
            qo[4 * i + 0] = q.x; qo[4 * i + 1] = q.y;
            qo[4 * i + 2] = q.z; qo[4 * i + 3] = q.w;
        }
    }

    __syncthreads();
    red[t] = lsum;
    __syncthreads();
    for (int s = 128; s > 0; s >>= 1) {
        if (t < s) red[t] += red[t + s];
        __syncthreads();
    }
    if (t == 0) g_bloss[blockIdx.x] = red[0];
}

// ============================================================
// 3) Finalize: loss + perplexity scalars
// ============================================================
__global__ void fin_kernel(float* __restrict__ out_loss,
                           float* __restrict__ out_perp) {
    __shared__ float sh[1024];
    const int t = threadIdx.x;

    float c = (float)g_counts[t];
    float p = c * (1.0f / (float)N_PTS);
    sh[t] = p * logf(p + 1e-10f);
    __syncthreads();
    for (int s = 512; s > 0; s >>= 1) {
        if (t < s) sh[t] += sh[t + s];
        __syncthreads();
    }
    float ent = sh[0];
    __syncthreads();

    sh[t] = (t < NCTAS) ? g_bloss[t] : 0.f;
    __syncthreads();
    for (int s = 512; s > 0; s >>= 1) {
        if (t < s) sh[t] += sh[t + s];
        __syncthreads();
    }
    if (t == 0) {
        *out_perp = expf(-ent);
        *out_loss = 1.25f * sh[0] / (float)((size_t)N_PTS * DIM);
    }
}

// ============================================================
// launch
// ============================================================
extern "C" void kernel_launch(void* const* d_in, const int* in_sizes, int n_in,
                              void* d_out, int out_size) {
    const float* x  = (const float*)d_in[0];   // [65536, 128] f32
    const float* cb = (const float*)d_in[1];   // [1024, 128]  f32
    float* out  = (float*)d_out;
    float* outq = out + 1;
    float* outp = out + 1 + (size_t)N_PTS * DIM;
    float* oute = outp + 1;

    static int attr_done = 0;
    if (!attr_done) {
        cudaFuncSetAttribute(vq_main, cudaFuncAttributeMaxDynamicSharedMemorySize,
                             SM_TOTAL);
        attr_done = 1;
    }

    prep_kernel<<<KCODES / 8, 128>>>(cb);
    vq_main<<<NCTAS, THREADS, SM_TOTAL>>>(x, cb, outq, oute);
    fin_kernel<<<1, 1024>>>(out, outp);
}